// round 17
// baseline (speedup 1.0000x reference)
#include <cuda_runtime.h>
#include <cuda_fp16.h>
#include <math.h>

// KANLayer: IN=128, OUT=128, SIZE=16384, BATCH=1024, NUM=5, K=3 -> 8 basis fns.
// R13: SINGLE fused kernel. Basis computed in-block during staging (each thread
//   owns one i -> 30 reciprocals once, 4 pure-FMA evals), fp16 swizzled smem.
//   Hot loop identical to R12 (Q=2, 4x LDS.128 basis, 6x STG.128, deferred
//   16-value butterfly reduction). No __device__ scratch, no K1 round-trip.

#define IN_DIM   128
#define OUT_DIM  128
#define BATCHSZ  1024
#define NB       8
#define NKNOT    12
#define TILE_B   8
#define NTHREADS 256

#define SW128(off) ((off) ^ (((off) >> 3) & 0x70))

__global__ __launch_bounds__(NTHREADS, 2)
void kan_fused_kernel(const float* __restrict__ x,
                      const float* __restrict__ grid,
                      const float* __restrict__ coef,
                      const float* __restrict__ scale_base,
                      const float* __restrict__ scale_sp,
                      const float* __restrict__ mask,
                      float* __restrict__ out)
{
    __shared__ __align__(1024) char Bsh[TILE_B * IN_DIM * NB * 2]; // 16KB swizzled
    __shared__ float4 xsh[TILE_B][IN_DIM / 4];
    __shared__ float4 ssh[TILE_B][IN_DIM / 4];

    const int tid  = threadIdx.x;
    const int b0   = blockIdx.x * TILE_B;
    const int warp = tid >> 5;
    const int L    = tid & 31;
    const int oA   = blockIdx.y * 16 + warp;
    const int oB   = oA + 8;

    // ================= staging: compute basis + silu in-block =================
    {
        const int i    = tid >> 1;     // 0..127, fixed per thread
        const int bsub = tid & 1;      // 0..1

        // knots for this i (sequential +-h to match reference fp order)
        float t[NKNOT];
        t[3] = grid[i * 6 + 0];
        t[4] = grid[i * 6 + 1];
        t[5] = grid[i * 6 + 2];
        t[6] = grid[i * 6 + 3];
        t[7] = grid[i * 6 + 4];
        t[8] = grid[i * 6 + 5];
        const float h = (t[8] - t[3]) * 0.2f;
        t[2] = t[3] - h;  t[1] = t[2] - h;  t[0]  = t[1]  - h;
        t[9] = t[8] + h;  t[10] = t[9] + h; t[11] = t[10] + h;

        // 30 reciprocal denominators, once per thread
        float r1[11], r2[10], r3[9];
        #pragma unroll
        for (int m = 0; m < 11; m++) r1[m] = __fdividef(1.0f, t[m + 1] - t[m]);
        #pragma unroll
        for (int m = 0; m < 10; m++) r2[m] = __fdividef(1.0f, t[m + 2] - t[m]);
        #pragma unroll
        for (int m = 0; m < 9;  m++) r3[m] = __fdividef(1.0f, t[m + 3] - t[m]);

        float* xs = (float*)xsh;
        float* ss = (float*)ssh;

        #pragma unroll
        for (int k = 0; k < 4; k++) {
            const int bl = bsub + 2 * k;          // local b 0..7
            const float xv = x[(b0 + bl) * IN_DIM + i];

            float Bv[NKNOT - 1];
            #pragma unroll
            for (int m = 0; m < NKNOT - 1; m++)
                Bv[m] = (xv >= t[m] && xv < t[m + 1]) ? 1.0f : 0.0f;
            #pragma unroll
            for (int m = 0; m < 10; m++)
                Bv[m] = (xv - t[m]) * r1[m] * Bv[m]
                      + (t[m + 2] - xv) * r1[m + 1] * Bv[m + 1];
            #pragma unroll
            for (int m = 0; m < 9; m++)
                Bv[m] = (xv - t[m]) * r2[m] * Bv[m]
                      + (t[m + 3] - xv) * r2[m + 1] * Bv[m + 1];
            #pragma unroll
            for (int m = 0; m < 8; m++)
                Bv[m] = (xv - t[m]) * r3[m] * Bv[m]
                      + (t[m + 4] - xv) * r3[m + 1] * Bv[m + 1];

            __half2 hp[4];
            hp[0] = __floats2half2_rn(Bv[0], Bv[1]);
            hp[1] = __floats2half2_rn(Bv[2], Bv[3]);
            hp[2] = __floats2half2_rn(Bv[4], Bv[5]);
            hp[3] = __floats2half2_rn(Bv[6], Bv[7]);
            *(uint4*)(Bsh + SW128((bl * IN_DIM + i) * 16)) = *(const uint4*)hp;

            xs[bl * IN_DIM + i] = xv;
            ss[bl * IN_DIM + i] = __fdividef(xv, 1.0f + __expf(-xv));
        }
    }

    // ---- per-thread constants for both o's ----
    float cfa[4][NB], cfb[4][NB];
    float4 msbA, mssA, msbB, mssB;
    {
        const int ibase = 4 * L;
        #pragma unroll
        for (int q = 0; q < 4; q++) {
            const int sA = oA * IN_DIM + ibase + q;
            const int sB = oB * IN_DIM + ibase + q;
            float4 a0 = *(const float4*)(coef + sA * NB);
            float4 a1 = *(const float4*)(coef + sA * NB + 4);
            cfa[q][0]=a0.x; cfa[q][1]=a0.y; cfa[q][2]=a0.z; cfa[q][3]=a0.w;
            cfa[q][4]=a1.x; cfa[q][5]=a1.y; cfa[q][6]=a1.z; cfa[q][7]=a1.w;
            float4 c0 = *(const float4*)(coef + sB * NB);
            float4 c1 = *(const float4*)(coef + sB * NB + 4);
            cfb[q][0]=c0.x; cfb[q][1]=c0.y; cfb[q][2]=c0.z; cfb[q][3]=c0.w;
            cfb[q][4]=c1.x; cfb[q][5]=c1.y; cfb[q][6]=c1.z; cfb[q][7]=c1.w;
        }
        const float4 sbA = *(const float4*)(scale_base + oA * IN_DIM + ibase);
        const float4 spA = *(const float4*)(scale_sp   + oA * IN_DIM + ibase);
        const float4 mkA = *(const float4*)(mask       + oA * IN_DIM + ibase);
        msbA = make_float4(mkA.x*sbA.x, mkA.y*sbA.y, mkA.z*sbA.z, mkA.w*sbA.w);
        mssA = make_float4(mkA.x*spA.x, mkA.y*spA.y, mkA.z*spA.z, mkA.w*spA.w);
        const float4 sbB = *(const float4*)(scale_base + oB * IN_DIM + ibase);
        const float4 spB = *(const float4*)(scale_sp   + oB * IN_DIM + ibase);
        const float4 mkB = *(const float4*)(mask       + oB * IN_DIM + ibase);
        msbB = make_float4(mkB.x*sbB.x, mkB.y*sbB.y, mkB.z*sbB.z, mkB.w*sbB.w);
        mssB = make_float4(mkB.x*spB.x, mkB.y*spB.y, mkB.z*spB.z, mkB.w*spB.w);
    }

    __syncthreads();

    const size_t P = (size_t)BATCHSZ * OUT_DIM * IN_DIM;
    float* y_out      = out;
    float* preacts    = out + (size_t)BATCHSZ * OUT_DIM;
    float* postacts   = preacts + P;
    float* postspline = postacts + P;

    float v[2 * TILE_B];   // per-lane partials: v[2b]=(b,oA), v[2b+1]=(b,oB)

    #pragma unroll
    for (int b = 0; b < TILE_B; b++) {
        const int bg = b0 + b;

        uint4 hv[4];
        #pragma unroll
        for (int q = 0; q < 4; q++) {
            const int off = (b * IN_DIM + 4 * L + q) * 16;
            hv[q] = *(const uint4*)(Bsh + SW128(off));
        }

        float spa[4], spb[4];
        #pragma unroll
        for (int q = 0; q < 4; q++) {
            const __half2* hh = (const __half2*)&hv[q];
            const float2 f0 = __half22float2(hh[0]);
            const float2 f1 = __half22float2(hh[1]);
            const float2 f2 = __half22float2(hh[2]);
            const float2 f3 = __half22float2(hh[3]);
            float sA, sB;
            sA = cfa[q][0] * f0.x;            sB = cfb[q][0] * f0.x;
            sA = fmaf(cfa[q][1], f0.y, sA);   sB = fmaf(cfb[q][1], f0.y, sB);
            sA = fmaf(cfa[q][2], f1.x, sA);   sB = fmaf(cfb[q][2], f1.x, sB);
            sA = fmaf(cfa[q][3], f1.y, sA);   sB = fmaf(cfb[q][3], f1.y, sB);
            sA = fmaf(cfa[q][4], f2.x, sA);   sB = fmaf(cfb[q][4], f2.x, sB);
            sA = fmaf(cfa[q][5], f2.y, sA);   sB = fmaf(cfb[q][5], f2.y, sB);
            sA = fmaf(cfa[q][6], f3.x, sA);   sB = fmaf(cfb[q][6], f3.x, sB);
            sA = fmaf(cfa[q][7], f3.y, sA);   sB = fmaf(cfb[q][7], f3.y, sB);
            spa[q] = sA; spb[q] = sB;
        }

        const float4 xv = xsh[b][L];
        const float4 sl = ssh[b][L];
        float4 ya, yb;
        ya.x = fmaf(mssA.x, spa[0], msbA.x * sl.x);
        ya.y = fmaf(mssA.y, spa[1], msbA.y * sl.y);
        ya.z = fmaf(mssA.z, spa[2], msbA.z * sl.z);
        ya.w = fmaf(mssA.w, spa[3], msbA.w * sl.w);
        yb.x = fmaf(mssB.x, spb[0], msbB.x * sl.x);
        yb.y = fmaf(mssB.y, spb[1], msbB.y * sl.y);
        yb.z = fmaf(mssB.z, spb[2], msbB.z * sl.z);
        yb.w = fmaf(mssB.w, spb[3], msbB.w * sl.w);

        const size_t baseA = ((size_t)bg * OUT_DIM + oA) * IN_DIM + 4 * L;
        const size_t baseB = ((size_t)bg * OUT_DIM + oB) * IN_DIM + 4 * L;
        const float4 sva = make_float4(spa[0], spa[1], spa[2], spa[3]);
        const float4 svb = make_float4(spb[0], spb[1], spb[2], spb[3]);
        __stcs((float4*)(preacts    + baseA), xv);
        __stcs((float4*)(postacts   + baseA), ya);
        __stcs((float4*)(postspline + baseA), sva);
        __stcs((float4*)(preacts    + baseB), xv);
        __stcs((float4*)(postacts   + baseB), yb);
        __stcs((float4*)(postspline + baseB), svb);

        v[2 * b]     = (ya.x + ya.y) + (ya.z + ya.w);
        v[2 * b + 1] = (yb.x + yb.y) + (yb.z + yb.w);
    }

    // ---- multi-value butterfly: 16 partials reduced with 16 shuffles ----
    #pragma unroll
    for (int m = 0; m < 8; m++) {                       // d=1 (splits b2)
        const float lo = v[m], hi = v[m + 8];
        const float send = (L & 1) ? lo : hi;
        const float recv = __shfl_xor_sync(0xffffffffu, send, 1);
        v[m] = ((L & 1) ? hi : lo) + recv;
    }
    #pragma unroll
    for (int m = 0; m < 4; m++) {                       // d=2 (splits b1)
        const float lo = v[m], hi = v[m + 4];
        const float send = (L & 2) ? lo : hi;
        const float recv = __shfl_xor_sync(0xffffffffu, send, 2);
        v[m] = ((L & 2) ? hi : lo) + recv;
    }
    #pragma unroll
    for (int m = 0; m < 2; m++) {                       // d=4 (splits b0)
        const float lo = v[m], hi = v[m + 2];
        const float send = (L & 4) ? lo : hi;
        const float recv = __shfl_xor_sync(0xffffffffu, send, 4);
        v[m] = ((L & 4) ? hi : lo) + recv;
    }
    {                                                   // d=8 (splits t)
        const float lo = v[0], hi = v[1];
        const float send = (L & 8) ? lo : hi;
        const float recv = __shfl_xor_sync(0xffffffffu, send, 8);
        v[0] = ((L & 8) ? hi : lo) + recv;
    }
    v[0] += __shfl_xor_sync(0xffffffffu, v[0], 16);     // d=16

    if (L < 16) {
        const int t  = (L >> 3) & 1;
        const int bl = ((L & 1) << 2) | (L & 2) | ((L >> 2) & 1); // b2 b1 b0
        const int o  = t ? oB : oA;
        y_out[(b0 + bl) * OUT_DIM + o] = v[0];
    }
}

// ---------------------------------------------------------------------------
extern "C" void kernel_launch(void* const* d_in, const int* in_sizes, int n_in,
                              void* d_out, int out_size)
{
    const float* x          = (const float*)d_in[0];
    const float* grid       = (const float*)d_in[1];
    const float* coef       = (const float*)d_in[2];
    const float* scale_base = (const float*)d_in[3];
    const float* scale_sp   = (const float*)d_in[4];
    const float* mask       = (const float*)d_in[5];
    float* out = (float*)d_out;

    dim3 g(BATCHSZ / TILE_B, OUT_DIM / 16);
    kan_fused_kernel<<<g, NTHREADS>>>(x, grid, coef, scale_base,
                                      scale_sp, mask, out);
}